// round 12
// baseline (speedup 1.0000x reference)
#include <cuda_runtime.h>
#include <cuda_bf16.h>
#include <math.h>

// Problem constants
#define NN 8192
#define KK 64
#define NB 1024
#define XLO (-6.0f)
#define BW_INVF (1024.0f / 12.0f)   // 1/bucket_width
#define RWIN 10                     // excluded pairs: |d| > 10*w = 0.1172 > 0.1123 support -> exp == 0.0f
#define GRID 256
#define TPB 256
#define NGRP 4                      // own buckets per block (stride 256 in bucket space)
#define NBIN (NGRP * 21)            // 84 local bins
#define SCAP 2048                   // staged capacity (worst block ~1100)

// -8192 * log2(e): EX2 argument scale (saves one FMUL vs __expf)
#define C2L (-11818.558f)

// Persistent global state (monotonic counter survives graph replays)
__device__ int   g_cnt;
__device__ float g_part[GRID];

__device__ __forceinline__ float ex2f(float y) {
    float r;
    asm("ex2.approx.f32 %0, %1;" : "=f"(r) : "f"(y));
    return r;
}

__device__ __forceinline__ int bin_of(float v, int blk) {
    int b = __float2int_rd((v - XLO) * BW_INVF);
    b = min(max(b, 0), NB - 1);
    int q = b + RWIN - blk;
    if (q < 0) return -1;
    int g = q >> 8, r = q & 255;
    return (r <= 2 * RWIN && g < NGRP) ? g * 21 + r : -1;
}

__global__ void __launch_bounds__(TPB)
gmm_fused(const float* __restrict__ x,
          const float* __restrict__ weight_logits,
          const float* __restrict__ means,
          const float* __restrict__ log_vars,
          float* __restrict__ out)
{
    __shared__ float raw[SCAP];                 // staged (atomic order)
    __shared__ float srt[SCAP];                 // staged (bin-major, value-sorted)
    __shared__ unsigned char bid[SCAP];         // bin id per staged slot
    __shared__ int   bcnt[NBIN];
    __shared__ int   boff[NBIN + 1];
    __shared__ int   bcur[NBIN];
    __shared__ int   ownoff[NGRP + 1];
    __shared__ float sa[KK], sc[KK], smu[KK];
    __shared__ float red[TPB / 32];
    __shared__ float fred[GRID];
    __shared__ int   slast;

    const int tid  = threadIdx.x;
    const int blk  = blockIdx.x;
    const int lane = tid & 31;
    const int w    = tid >> 5;
    const unsigned FULL = 0xffffffffu;

    // ---- GMM constants (warp 0, redundant per block) -------------------
    if (w == 0) {
        const float TWO_PI = 6.283185307179586f;
        float l0 = weight_logits[lane], l1 = weight_logits[lane + 32];
        float m = fmaxf(l0, l1);
        #pragma unroll
        for (int o = 16; o > 0; o >>= 1) m = fmaxf(m, __shfl_xor_sync(FULL, m, o));
        float e0 = expf(l0 - m), e1 = expf(l1 - m);
        float s = e0 + e1;
        #pragma unroll
        for (int o = 16; o > 0; o >>= 1) s += __shfl_xor_sync(FULL, s, o);
        float invs = 1.0f / s;

        float var0 = expf(log_vars[lane]);
        sa[lane]  = e0 * invs * rsqrtf(TWO_PI * var0);
        sc[lane]  = -0.5f / var0;
        smu[lane] = means[lane];
        float var1 = expf(log_vars[lane + 32]);
        sa[lane + 32]  = e1 * invs * rsqrtf(TWO_PI * var1);
        sc[lane + 32]  = -0.5f / var1;
        smu[lane + 32] = means[lane + 32];
    }

    if (tid < NBIN) bcnt[tid] = 0;
    __syncthreads();

    // ---- P1: count pass (float4 loads; L1-hot) -------------------------
    const float4* x4 = (const float4*)x;
    #pragma unroll
    for (int t = 0; t < NN / (TPB * 4); ++t) {
        float4 q = x4[t * TPB + tid];
        int ba = bin_of(q.x, blk); if (ba >= 0) atomicAdd(&bcnt[ba], 1);
        int bb = bin_of(q.y, blk); if (bb >= 0) atomicAdd(&bcnt[bb], 1);
        int bc = bin_of(q.z, blk); if (bc >= 0) atomicAdd(&bcnt[bc], 1);
        int bd = bin_of(q.w, blk); if (bd >= 0) atomicAdd(&bcnt[bd], 1);
    }
    __syncthreads();

    // ---- P2: prefix over 84 bins (warp 0, 3/lane) + own prefix (warp 1) ----
    if (w == 0) {
        int base = lane * 3;
        int c[3]; int tot = 0;
        #pragma unroll
        for (int i = 0; i < 3; ++i) {
            int idx = base + i;
            c[i] = (idx < NBIN) ? bcnt[idx] : 0;
            tot += c[i];
        }
        int incl = tot;
        #pragma unroll
        for (int o = 1; o < 32; o <<= 1) {
            int n = __shfl_up_sync(FULL, incl, o);
            if (lane >= o) incl += n;
        }
        int run = incl - tot;
        #pragma unroll
        for (int i = 0; i < 3; ++i) {
            int idx = base + i;
            if (idx < NBIN) boff[idx] = run;
            run += c[i];
        }
        if (lane == 31) boff[NBIN] = incl;   // total staged S
    }
    if (w == 1 && lane < NGRP) {
        int oc = bcnt[lane * 21 + RWIN];     // own bucket bin (r=10)
        int incl = oc;
        #pragma unroll
        for (int o = 1; o < NGRP; o <<= 1) {
            int n = __shfl_up_sync(0xfu, incl, o, NGRP);
            if (lane >= o) incl += n;
        }
        ownoff[lane] = incl - oc;
        if (lane == NGRP - 1) ownoff[NGRP] = incl;
    }
    __syncthreads();
    if (tid < NBIN) bcur[tid] = boff[tid];
    __syncthreads();

    // ---- P3: place pass (atomic order; canonicalized next) -------------
    #pragma unroll
    for (int t = 0; t < NN / (TPB * 4); ++t) {
        float4 q = x4[t * TPB + tid];
        int ba = bin_of(q.x, blk);
        if (ba >= 0) { int p = atomicAdd(&bcur[ba], 1); raw[p] = q.x; bid[p] = (unsigned char)ba; }
        int bb = bin_of(q.y, blk);
        if (bb >= 0) { int p = atomicAdd(&bcur[bb], 1); raw[p] = q.y; bid[p] = (unsigned char)bb; }
        int bc = bin_of(q.z, blk);
        if (bc >= 0) { int p = atomicAdd(&bcur[bc], 1); raw[p] = q.z; bid[p] = (unsigned char)bc; }
        int bd = bin_of(q.w, blk);
        if (bd >= 0) { int p = atomicAdd(&bcur[bd], 1); raw[p] = q.w; bid[p] = (unsigned char)bd; }
    }
    __syncthreads();

    // ---- P4: element-parallel rank sort within bins (deterministic) ----
    const int S = boff[NBIN];
    for (int s = tid; s < S; s += TPB) {
        int bin = bid[s];
        int lo = boff[bin], hi = boff[bin + 1];
        float val = raw[s];
        int rank = 0;
        for (int u = lo; u < hi; ++u) {
            float o = raw[u];
            rank += (o < val) || (o == val && u < s);
        }
        srt[lo + rank] = val;
    }
    __syncthreads();

    // ---- P5: KDE + mixture. 8 threads per own element ------------------
    const float invZ = (float)(1.0 / (0.0078125 * 2.5066282746310002 * 8192.0));
    const int M   = ownoff[NGRP];
    const int Mup = (M + 31) & ~31;
    const int e0  = tid >> 3;            // 0..31
    const int p   = tid & 7;

    float acc = 0.0f;
    for (int e = e0; e < Mup; e += TPB / 8) {
        bool active = (e < M);
        int g = 0;
        if (active)
            g = (e >= ownoff[1]) + (e >= ownoff[2]) + (e >= ownoff[3]);

        float xi = 0.0f;
        int wlo = 0, whi = 0;
        if (active) {
            int pos = e - ownoff[g];
            xi  = srt[boff[g * 21 + RWIN] + pos];
            wlo = boff[g * 21];
            whi = boff[g * 21 + 21];
        }

        // this part's strided share of the group window
        float s0 = 0.f, s1 = 0.f;
        int t = wlo + p;
        for (; t + 8 < whi; t += 16) {
            float d0 = xi - srt[t];
            float d1 = xi - srt[t + 8];
            s0 += ex2f(C2L * d0 * d0);
            s1 += ex2f(C2L * d1 * d1);
        }
        for (; t < whi; t += 8) {
            float d = xi - srt[t];
            s0 += ex2f(C2L * d * d);
        }
        float kde = s0 + s1;

        // this part's 8 mixture components
        float m = 0.0f;
        #pragma unroll
        for (int k = p * 8; k < p * 8 + 8; ++k) {
            float d = xi - smu[k];
            m += sa[k] * __expf(sc[k] * d * d);
        }

        float part = active ? (m - invZ * kde) : 0.0f;
        part += __shfl_xor_sync(FULL, part, 4, 8);
        part += __shfl_xor_sync(FULL, part, 2, 8);
        part += __shfl_xor_sync(FULL, part, 1, 8);
        if (p == 0 && active) acc += part * part;
    }

    // ---- block reduction (fixed order) ---------------------------------
    #pragma unroll
    for (int o = 16; o > 0; o >>= 1) acc += __shfl_xor_sync(FULL, acc, o);
    if (lane == 0) red[w] = acc;
    __syncthreads();
    if (w == 0) {
        float bsum = (lane < TPB / 32) ? red[lane] : 0.0f;
        #pragma unroll
        for (int o = 16; o > 0; o >>= 1) bsum += __shfl_xor_sync(FULL, bsum, o);
        if (lane == 0) {
            g_part[blk] = bsum;
            __threadfence();
            int old = atomicAdd(&g_cnt, 1);
            slast = (((old + 1) & (GRID - 1)) == 0);
        }
    }
    __syncthreads();

    // ---- last block: fixed-order final sum ------------------------------
    if (slast) {
        volatile float* vp = g_part;
        fred[tid] = vp[tid];
        __syncthreads();
        #pragma unroll
        for (int off = GRID / 2; off > 0; off >>= 1) {
            if (tid < off && tid + off < GRID) fred[tid] += fred[tid + off];
            __syncthreads();
        }
        if (tid == 0) out[0] = fred[0];
    }
}

// ---------------------------------------------------------------------------
extern "C" void kernel_launch(void* const* d_in, const int* in_sizes, int n_in,
                              void* d_out, int out_size)
{
    const float* x             = (const float*)d_in[0];
    const float* weight_logits = (const float*)d_in[1];
    const float* means         = (const float*)d_in[2];
    const float* log_vars      = (const float*)d_in[3];
    float* out = (float*)d_out;

    gmm_fused<<<GRID, TPB>>>(x, weight_logits, means, log_vars, out);
}

// round 13
// speedup vs baseline: 1.1313x; 1.1313x over previous
#include <cuda_runtime.h>
#include <cuda_bf16.h>
#include <math.h>

// Problem constants
#define NN 8192
#define KK 64
#define NB 1024
#define XLO (-6.0f)
#define BW_INVF (1024.0f / 12.0f)   // 1/bucket_width
#define RWIN 10                     // excluded pairs: |d| > 10*w = 0.1172 > support -> exp == 0.0f
#define GRID 256
#define TPB 512
#define NGRP 4                      // own buckets per block (stride 256 in bucket space)
#define NBIN (NGRP * 21)            // 84 local bins
#define SCAP 2048                   // staged capacity (worst block ~1300)
#define PSPLIT 16                   // threads per own element in P5

// -8192 * log2(e): EX2 argument scale
#define C2L (-11818.558f)

// Persistent global state (monotonic counter survives graph replays)
__device__ int   g_cnt;
__device__ float g_part[GRID];

__device__ __forceinline__ float ex2f(float y) {
    float r;
    asm("ex2.approx.f32 %0, %1;" : "=f"(r) : "f"(y));
    return r;
}

__device__ __forceinline__ int bin_of(float v, int blk) {
    int b = __float2int_rd((v - XLO) * BW_INVF);
    b = min(max(b, 0), NB - 1);
    int q = b + RWIN - blk;
    if (q < 0) return -1;
    int g = q >> 8, r = q & 255;
    return (r <= 2 * RWIN && g < NGRP) ? g * 21 + r : -1;
}

__global__ void __launch_bounds__(TPB, 2)
gmm_fused(const float* __restrict__ x,
          const float* __restrict__ weight_logits,
          const float* __restrict__ means,
          const float* __restrict__ log_vars,
          float* __restrict__ out)
{
    __shared__ float raw[SCAP];                 // staged (atomic order)
    __shared__ float srt[SCAP];                 // staged (bin-major, value-sorted)
    __shared__ unsigned char bid[SCAP];         // bin id per staged slot
    __shared__ int   bcnt[NBIN];
    __shared__ int   boff[NBIN + 1];
    __shared__ int   bcur[NBIN];
    __shared__ int   ownoff[NGRP + 1];
    __shared__ float sa[KK], sc[KK], smu[KK];
    __shared__ float red[TPB / 32];
    __shared__ float fred[GRID];
    __shared__ int   slast;

    const int tid  = threadIdx.x;
    const int blk  = blockIdx.x;
    const int lane = tid & 31;
    const int w    = tid >> 5;
    const unsigned FULL = 0xffffffffu;

    // ---- GMM constants (warp 0, redundant per block) -------------------
    if (w == 0) {
        const float TWO_PI = 6.283185307179586f;
        float l0 = weight_logits[lane], l1 = weight_logits[lane + 32];
        float m = fmaxf(l0, l1);
        #pragma unroll
        for (int o = 16; o > 0; o >>= 1) m = fmaxf(m, __shfl_xor_sync(FULL, m, o));
        float e0 = expf(l0 - m), e1 = expf(l1 - m);
        float s = e0 + e1;
        #pragma unroll
        for (int o = 16; o > 0; o >>= 1) s += __shfl_xor_sync(FULL, s, o);
        float invs = 1.0f / s;

        float var0 = expf(log_vars[lane]);
        sa[lane]  = e0 * invs * rsqrtf(TWO_PI * var0);
        sc[lane]  = -0.5f / var0;
        smu[lane] = means[lane];
        float var1 = expf(log_vars[lane + 32]);
        sa[lane + 32]  = e1 * invs * rsqrtf(TWO_PI * var1);
        sc[lane + 32]  = -0.5f / var1;
        smu[lane + 32] = means[lane + 32];
    }

    if (tid < NBIN) bcnt[tid] = 0;
    __syncthreads();

    // ---- P1: single classify pass with register cache (16 elems/thread) ----
    float vv[16];
    int   vbin[16];
    {
        const float4* x4 = (const float4*)x;
        #pragma unroll
        for (int t = 0; t < 4; ++t) {
            float4 q = x4[t * TPB + tid];
            vv[t * 4 + 0] = q.x; vv[t * 4 + 1] = q.y;
            vv[t * 4 + 2] = q.z; vv[t * 4 + 3] = q.w;
        }
        #pragma unroll
        for (int t = 0; t < 16; ++t) {
            vbin[t] = bin_of(vv[t], blk);
            if (vbin[t] >= 0) atomicAdd(&bcnt[vbin[t]], 1);
        }
    }
    __syncthreads();

    // ---- P2: prefix over 84 bins (warp 0, 3/lane) + own prefix (warp 1) ----
    if (w == 0) {
        int base = lane * 3;
        int c[3]; int tot = 0;
        #pragma unroll
        for (int i = 0; i < 3; ++i) {
            int idx = base + i;
            c[i] = (idx < NBIN) ? bcnt[idx] : 0;
            tot += c[i];
        }
        int incl = tot;
        #pragma unroll
        for (int o = 1; o < 32; o <<= 1) {
            int n = __shfl_up_sync(FULL, incl, o);
            if (lane >= o) incl += n;
        }
        int run = incl - tot;
        #pragma unroll
        for (int i = 0; i < 3; ++i) {
            int idx = base + i;
            if (idx < NBIN) boff[idx] = run;
            run += c[i];
        }
        if (lane == 31) boff[NBIN] = incl;   // total staged S
    }
    if (w == 1 && lane < NGRP) {
        int oc = bcnt[lane * 21 + RWIN];     // own bucket bin (r=10)
        int incl = oc;
        #pragma unroll
        for (int o = 1; o < NGRP; o <<= 1) {
            int n = __shfl_up_sync(0xfu, incl, o, NGRP);
            if (lane >= o) incl += n;
        }
        ownoff[lane] = incl - oc;
        if (lane == NGRP - 1) ownoff[NGRP] = incl;
    }
    __syncthreads();
    if (tid < NBIN) bcur[tid] = boff[tid];
    __syncthreads();

    // ---- P3: place from register cache (atomic order; canonicalized next) ----
    #pragma unroll
    for (int t = 0; t < 16; ++t) {
        int bin = vbin[t];
        if (bin >= 0) {
            int p = atomicAdd(&bcur[bin], 1);
            raw[p] = vv[t]; bid[p] = (unsigned char)bin;
        }
    }
    __syncthreads();

    // ---- P4: element-parallel rank sort within bins (deterministic) ----
    const int S = boff[NBIN];
    for (int s = tid; s < S; s += TPB) {
        int bin = bid[s];
        int lo = boff[bin], hi = boff[bin + 1];
        float val = raw[s];
        int rank = 0;
        for (int u = lo; u < hi; ++u) {
            float o = raw[u];
            rank += (o < val) || (o == val && u < s);
        }
        srt[lo + rank] = val;
    }
    __syncthreads();

    // ---- P5: KDE + mixture. 16 threads per own element, contiguous parts ----
    const float invZ = (float)(1.0 / (0.0078125 * 2.5066282746310002 * 8192.0));
    const int M    = ownoff[NGRP];                  // own elements (~32)
    const int ESL  = TPB / PSPLIT;                  // 32 element-slots per pass
    const int Mup  = (M + ESL - 1) / ESL * ESL;
    const int e0   = tid >> 4;                      // 0..31
    const int p    = tid & (PSPLIT - 1);

    float acc = 0.0f;
    for (int e = e0; e < Mup; e += ESL) {
        bool active = (e < M);
        int g = 0;
        if (active)
            g = (e >= ownoff[1]) + (e >= ownoff[2]) + (e >= ownoff[3]);

        float xi = 0.0f;
        int a = 0, b = 0;
        if (active) {
            int pos = e - ownoff[g];
            xi = srt[boff[g * 21 + RWIN] + pos];
            int wlo = boff[g * 21];
            int len = boff[g * 21 + 21] - wlo;
            a = wlo + (p * len) / PSPLIT;
            b = wlo + ((p + 1) * len) / PSPLIT;
        }

        // contiguous share, unroll-4, 4 independent accumulators (LDS MLP=4)
        float s0 = 0.f, s1 = 0.f, s2 = 0.f, s3 = 0.f;
        int k = a;
        for (; k + 4 <= b; k += 4) {
            float u0 = srt[k + 0], u1 = srt[k + 1];
            float u2 = srt[k + 2], u3 = srt[k + 3];
            float d0 = xi - u0, d1 = xi - u1, d2 = xi - u2, d3 = xi - u3;
            s0 += ex2f(C2L * d0 * d0);
            s1 += ex2f(C2L * d1 * d1);
            s2 += ex2f(C2L * d2 * d2);
            s3 += ex2f(C2L * d3 * d3);
        }
        for (; k < b; ++k) {
            float d = xi - srt[k];
            s0 += ex2f(C2L * d * d);
        }
        float kde = (s0 + s1) + (s2 + s3);

        // this part's 4 mixture components
        float m = 0.0f;
        #pragma unroll
        for (int c = p * 4; c < p * 4 + 4; ++c) {
            float d = xi - smu[c];
            m += sa[c] * __expf(sc[c] * d * d);
        }

        float part = active ? (m - invZ * kde) : 0.0f;
        // combine the 16 parts (fixed order; width-16 butterfly)
        part += __shfl_xor_sync(FULL, part, 8, 16);
        part += __shfl_xor_sync(FULL, part, 4, 16);
        part += __shfl_xor_sync(FULL, part, 2, 16);
        part += __shfl_xor_sync(FULL, part, 1, 16);
        if (p == 0 && active) acc += part * part;
    }

    // ---- block reduction (fixed order) ---------------------------------
    #pragma unroll
    for (int o = 16; o > 0; o >>= 1) acc += __shfl_xor_sync(FULL, acc, o);
    if (lane == 0) red[w] = acc;
    __syncthreads();
    if (w == 0) {
        float bsum = (lane < TPB / 32) ? red[lane] : 0.0f;
        #pragma unroll
        for (int o = 16; o > 0; o >>= 1) bsum += __shfl_xor_sync(FULL, bsum, o);
        if (lane == 0) {
            g_part[blk] = bsum;
            __threadfence();
            int old = atomicAdd(&g_cnt, 1);
            slast = (((old + 1) & (GRID - 1)) == 0);
        }
    }
    __syncthreads();

    // ---- last block: fixed-order final sum ------------------------------
    if (slast) {
        if (tid < GRID) {
            volatile float* vp = g_part;
            fred[tid] = vp[tid];
        }
        __syncthreads();
        #pragma unroll
        for (int off = GRID / 2; off > 0; off >>= 1) {
            if (tid < off) fred[tid] += fred[tid + off];
            __syncthreads();
        }
        if (tid == 0) out[0] = fred[0];
    }
}

// ---------------------------------------------------------------------------
extern "C" void kernel_launch(void* const* d_in, const int* in_sizes, int n_in,
                              void* d_out, int out_size)
{
    const float* x             = (const float*)d_in[0];
    const float* weight_logits = (const float*)d_in[1];
    const float* means         = (const float*)d_in[2];
    const float* log_vars      = (const float*)d_in[3];
    float* out = (float*)d_out;

    gmm_fused<<<GRID, TPB>>>(x, weight_logits, means, log_vars, out);
}